// round 6
// baseline (speedup 1.0000x reference)
#include <cuda_runtime.h>
#include <cuda_bf16.h>
#include <cstdint>

// Problem constants (match reference_code)
#define NN 50000
#define EE 800000
#define FIN 256
#define FOUT 64

#define NBLK 49   // ceil(NN / 1024)

// Scratch (no cudaMalloc allowed) — static __device__ globals.
__device__ int   g_cnt[NN];          // in-degree (w/o self loop)
__device__ int   g_fill[NN];         // bucket fill cursor (pre-init to offsets)
__device__ int   g_off[NN + 1];      // CSR offsets
__device__ int   g_bsum[64];         // per-block sums for scan
__device__ int2  g_nbr2[EE];         // CSR: {src node, norm bits} per incoming edge
__device__ float g_deg[NN];          // dinv = rsqrt(deg)
__device__ float g_h[NN * FOUT];     // h = x @ W

// ---------------------------------------------------------------------------
// K1: zero counters
__global__ void k_zero() {
    int i = blockIdx.x * blockDim.x + threadIdx.x;
    if (i < NN) g_cnt[i] = 0;
}

// K2: in-degree count over edge dst (4 edges/thread, int4 loads)
__global__ void k_count(const int* __restrict__ dst) {
    int e0 = (blockIdx.x * blockDim.x + threadIdx.x) * 4;
    if (e0 >= EE) return;
    int4 d4 = *reinterpret_cast<const int4*>(dst + e0);
    atomicAdd(&g_cnt[d4.x], 1);
    atomicAdd(&g_cnt[d4.y], 1);
    atomicAdd(&g_cnt[d4.z], 1);
    atomicAdd(&g_cnt[d4.w], 1);
}

// K3a: per-block (1024 elems) sums, coalesced
__global__ __launch_bounds__(1024) void k_scan_a() {
    __shared__ int ws[32];
    const int t = threadIdx.x;
    int idx = blockIdx.x * 1024 + t;
    int v = (idx < NN) ? g_cnt[idx] : 0;
    for (int o = 16; o > 0; o >>= 1) v += __shfl_down_sync(0xffffffffu, v, o);
    if ((t & 31) == 0) ws[t >> 5] = v;
    __syncthreads();
    if (t < 32) {
        int s = ws[t];
        for (int o = 16; o > 0; o >>= 1) s += __shfl_down_sync(0xffffffffu, s, o);
        if (t == 0) g_bsum[blockIdx.x] = s;
    }
}

// K3b: per-block exclusive scan -> g_off, g_fill (cursor), g_deg.
// Each block computes its own global prefix from g_bsum (warp 1), no extra kernel.
__global__ __launch_bounds__(1024) void k_scan_c() {
    __shared__ int ws[32];
    __shared__ int bpre_s;
    const int t = threadIdx.x;
    const int lane = t & 31;
    const int wid = t >> 5;
    int idx = blockIdx.x * 1024 + t;
    int c = (idx < NN) ? g_cnt[idx] : 0;

    // per-warp inclusive scan
    int incl = c;
    for (int o = 1; o < 32; o <<= 1) {
        int u = __shfl_up_sync(0xffffffffu, incl, o);
        if (lane >= o) incl += u;
    }
    if (lane == 31) ws[wid] = incl;

    // warp 1: this block's global prefix (sum of earlier block sums)
    if (wid == 1) {
        int accp = 0;
        for (int j = lane; j < blockIdx.x; j += 32) accp += g_bsum[j];
        for (int o = 16; o > 0; o >>= 1) accp += __shfl_down_sync(0xffffffffu, accp, o);
        if (lane == 0) bpre_s = accp;
    }
    __syncthreads();
    if (wid == 0) {
        int wv = ws[lane];
        for (int o = 1; o < 32; o <<= 1) {
            int u = __shfl_up_sync(0xffffffffu, wv, o);
            if (lane >= o) wv += u;
        }
        ws[lane] = wv;
    }
    __syncthreads();
    int excl = incl - c + (wid ? ws[wid - 1] : 0);

    if (idx < NN) {
        int off = bpre_s + excl;
        g_off[idx]  = off;
        g_fill[idx] = off;
        g_deg[idx]  = rsqrtf((float)(c + 1));
    }
    if (blockIdx.x == 0 && t == 0) g_off[NN] = EE;
}

// K4: bucket fill — cursor holds offsets; 4 edges/thread; fuse norm compute.
__global__ void k_fill(const int* __restrict__ src, const int* __restrict__ dst) {
    int e0 = (blockIdx.x * blockDim.x + threadIdx.x) * 4;
    if (e0 >= EE) return;
    int4 s4 = *reinterpret_cast<const int4*>(src + e0);
    int4 d4 = *reinterpret_cast<const int4*>(dst + e0);
    float ds0 = g_deg[s4.x], ds1 = g_deg[s4.y], ds2 = g_deg[s4.z], ds3 = g_deg[s4.w];
    float dd0 = g_deg[d4.x], dd1 = g_deg[d4.y], dd2 = g_deg[d4.z], dd3 = g_deg[d4.w];
    int p0 = atomicAdd(&g_fill[d4.x], 1);
    int p1 = atomicAdd(&g_fill[d4.y], 1);
    int p2 = atomicAdd(&g_fill[d4.z], 1);
    int p3 = atomicAdd(&g_fill[d4.w], 1);
    g_nbr2[p0] = make_int2(s4.x, __float_as_int(ds0 * dd0));
    g_nbr2[p1] = make_int2(s4.y, __float_as_int(ds1 * dd1));
    g_nbr2[p2] = make_int2(s4.z, __float_as_int(ds2 * dd2));
    g_nbr2[p3] = make_int2(s4.w, __float_as_int(ds3 * dd3));
}

// ---------------------------------------------------------------------------
// K5: mma.sync bf16 GEMM  h = x @ W  with split-bf16.
// 8 warps/CTA, each warp: 16 rows x all 64 cols (x read once).
// W pre-packed in smem as mma b-fragments: uint4 {bh0,bh1,bl0,bl1}
// at index [n][s*4+tig], stride 68 uint4/n (conflict-free LDS.128).

#define FRAG_STRIDE 68                      // uint4 units per n
#define GEMM_SMEM (64 * FRAG_STRIDE * 16)   // 69632 bytes

__device__ __forceinline__ uint32_t pk2(float lo, float hi) {
    uint32_t d;
    asm("cvt.rn.bf16x2.f32 %0, %1, %2;" : "=r"(d) : "f"(hi), "f"(lo));
    return d;
}
__device__ __forceinline__ float f_lo16(uint32_t u) { return __uint_as_float(u << 16); }
__device__ __forceinline__ float f_hi16(uint32_t u) { return __uint_as_float(u & 0xffff0000u); }

__device__ __forceinline__ void mma_bf16(float* c, const uint32_t* a, uint32_t b0, uint32_t b1) {
    asm volatile(
        "mma.sync.aligned.m16n8k16.row.col.f32.bf16.bf16.f32 "
        "{%0,%1,%2,%3}, {%4,%5,%6,%7}, {%8,%9}, {%0,%1,%2,%3};"
        : "+f"(c[0]), "+f"(c[1]), "+f"(c[2]), "+f"(c[3])
        : "r"(a[0]), "r"(a[1]), "r"(a[2]), "r"(a[3]), "r"(b0), "r"(b1));
}

__global__ __launch_bounds__(256, 3) void k_gemm_mma(
    const float* __restrict__ x, const float* __restrict__ W)
{
    extern __shared__ __align__(16) uint4 Bf[];

    const int t    = threadIdx.x;
    const int wid  = t >> 5;
    const int lane = t & 31;
    const int g    = lane >> 2;
    const int tig  = lane & 3;

    // ---- stage W as pre-packed b-fragments: 4096 entries / 256 thr ----
#pragma unroll
    for (int i = 0; i < 16; ++i) {
        int e  = t + i * 256;
        int n  = e >> 6;
        int s  = (e >> 2) & 15;
        int tg = e & 3;
        int kb = s * 16 + tg * 2;
        float w0 = W[kb * FOUT + n];
        float w1 = W[(kb + 1) * FOUT + n];
        float w2 = W[(kb + 8) * FOUT + n];
        float w3 = W[(kb + 9) * FOUT + n];
        uint32_t h01 = pk2(w0, w1);
        uint32_t h23 = pk2(w2, w3);
        uint32_t l01 = pk2(w0 - f_lo16(h01), w1 - f_hi16(h01));
        uint32_t l23 = pk2(w2 - f_lo16(h23), w3 - f_hi16(h23));
        Bf[n * FRAG_STRIDE + s * 4 + tg] = make_uint4(h01, h23, l01, l23);
    }
    __syncthreads();

    // ---- warp tiling: warp wid -> rows [row0, row0+16), all 64 cols ----
    const int row0 = blockIdx.x * 128 + wid * 16;
    const int r1 = row0 + g;
    const int r2 = r1 + 8;
    const bool v1 = (r1 < NN);
    const bool v2 = (r2 < NN);
    const float* xr1 = x + (size_t)r1 * FIN;
    const float* xr2 = x + (size_t)r2 * FIN;

    float acc[8][4];
#pragma unroll
    for (int i = 0; i < 8; ++i)
#pragma unroll
        for (int j = 0; j < 4; ++j) acc[i][j] = 0.0f;

#pragma unroll 4
    for (int s = 0; s < 16; ++s) {
        const int kb = s * 16 + tig * 2;

        float2 p0 = v1 ? *reinterpret_cast<const float2*>(xr1 + kb)     : make_float2(0.f, 0.f);
        float2 p1 = v2 ? *reinterpret_cast<const float2*>(xr2 + kb)     : make_float2(0.f, 0.f);
        float2 p2 = v1 ? *reinterpret_cast<const float2*>(xr1 + kb + 8) : make_float2(0.f, 0.f);
        float2 p3 = v2 ? *reinterpret_cast<const float2*>(xr2 + kb + 8) : make_float2(0.f, 0.f);

        uint32_t ah[4], al[4];
        ah[0] = pk2(p0.x, p0.y); al[0] = pk2(p0.x - f_lo16(ah[0]), p0.y - f_hi16(ah[0]));
        ah[1] = pk2(p1.x, p1.y); al[1] = pk2(p1.x - f_lo16(ah[1]), p1.y - f_hi16(ah[1]));
        ah[2] = pk2(p2.x, p2.y); al[2] = pk2(p2.x - f_lo16(ah[2]), p2.y - f_hi16(ah[2]));
        ah[3] = pk2(p3.x, p3.y); al[3] = pk2(p3.x - f_lo16(ah[3]), p3.y - f_hi16(ah[3]));

        const int fbase = s * 4 + tig;
#pragma unroll
        for (int nt = 0; nt < 8; ++nt) {
            uint4 f = Bf[(nt * 8 + g) * FRAG_STRIDE + fbase];
            mma_bf16(acc[nt], ah, f.x, f.y);   // hi*hi
            mma_bf16(acc[nt], ah, f.z, f.w);   // hi*lo
            mma_bf16(acc[nt], al, f.x, f.y);   // lo*hi
        }
    }

    // ---- epilogue: write h ----
#pragma unroll
    for (int nt = 0; nt < 8; ++nt) {
        int c0 = nt * 8 + tig * 2;
        if (v1)
            *reinterpret_cast<float2*>(&g_h[(size_t)r1 * FOUT + c0]) =
                make_float2(acc[nt][0], acc[nt][1]);
        if (v2)
            *reinterpret_cast<float2*>(&g_h[(size_t)r2 * FOUT + c0]) =
                make_float2(acc[nt][2], acc[nt][3]);
    }
}

// ---------------------------------------------------------------------------
// K6: CSR gather. 2 nodes/warp (16 lanes x float4), norm pre-fused in g_nbr2,
// neighbor loop unrolled x4.
__global__ __launch_bounds__(256) void k_gather(
    const float* __restrict__ bias, float* __restrict__ out)
{
    const int warp = blockIdx.x * 8 + (threadIdx.x >> 5);
    const int lane = threadIdx.x & 31;
    const int half = lane >> 4;
    const int hl   = lane & 15;
    const int node = warp * 2 + half;
    if (node >= NN) return;

    const float dinv = g_deg[node];
    const int beg = g_off[node];
    const int end = g_off[node + 1];

    // self-loop term: h[node] * dinv^2
    float4 a = *reinterpret_cast<const float4*>(&g_h[(size_t)node * FOUT + hl * 4]);
    const float sl = dinv * dinv;
    a.x *= sl; a.y *= sl; a.z *= sl; a.w *= sl;

    int j = beg;
    for (; j + 4 <= end; j += 4) {
        int2 e0 = g_nbr2[j];
        int2 e1 = g_nbr2[j + 1];
        int2 e2 = g_nbr2[j + 2];
        int2 e3 = g_nbr2[j + 3];
        float4 v0 = *reinterpret_cast<const float4*>(&g_h[(size_t)e0.x * FOUT + hl * 4]);
        float4 v1 = *reinterpret_cast<const float4*>(&g_h[(size_t)e1.x * FOUT + hl * 4]);
        float4 v2 = *reinterpret_cast<const float4*>(&g_h[(size_t)e2.x * FOUT + hl * 4]);
        float4 v3 = *reinterpret_cast<const float4*>(&g_h[(size_t)e3.x * FOUT + hl * 4]);
        float n0 = __int_as_float(e0.y), n1 = __int_as_float(e1.y);
        float n2 = __int_as_float(e2.y), n3 = __int_as_float(e3.y);
        a.x = fmaf(v0.x, n0, a.x); a.y = fmaf(v0.y, n0, a.y);
        a.z = fmaf(v0.z, n0, a.z); a.w = fmaf(v0.w, n0, a.w);
        a.x = fmaf(v1.x, n1, a.x); a.y = fmaf(v1.y, n1, a.y);
        a.z = fmaf(v1.z, n1, a.z); a.w = fmaf(v1.w, n1, a.w);
        a.x = fmaf(v2.x, n2, a.x); a.y = fmaf(v2.y, n2, a.y);
        a.z = fmaf(v2.z, n2, a.z); a.w = fmaf(v2.w, n2, a.w);
        a.x = fmaf(v3.x, n3, a.x); a.y = fmaf(v3.y, n3, a.y);
        a.z = fmaf(v3.z, n3, a.z); a.w = fmaf(v3.w, n3, a.w);
    }
    for (; j < end; ++j) {
        int2 e0 = g_nbr2[j];
        float n0 = __int_as_float(e0.y);
        float4 v0 = *reinterpret_cast<const float4*>(&g_h[(size_t)e0.x * FOUT + hl * 4]);
        a.x = fmaf(v0.x, n0, a.x); a.y = fmaf(v0.y, n0, a.y);
        a.z = fmaf(v0.z, n0, a.z); a.w = fmaf(v0.w, n0, a.w);
    }

    float4 bb = *reinterpret_cast<const float4*>(bias + hl * 4);
    a.x = fmaxf(a.x + bb.x, 0.f);
    a.y = fmaxf(a.y + bb.y, 0.f);
    a.z = fmaxf(a.z + bb.z, 0.f);
    a.w = fmaxf(a.w + bb.w, 0.f);
    *reinterpret_cast<float4*>(&out[(size_t)node * FOUT + hl * 4]) = a;
}

// ---------------------------------------------------------------------------
extern "C" void kernel_launch(void* const* d_in, const int* in_sizes, int n_in,
                              void* d_out, int out_size)
{
    const float* x   = (const float*)d_in[0];   // [N, 256]
    const int*   adj = (const int*)d_in[1];     // [2, E]
    const float* W   = (const float*)d_in[2];   // [256, 64]
    const float* b   = (const float*)d_in[3];   // [64]
    float*       out = (float*)d_out;           // [N, 64]

    const int* src = adj;
    const int* dst = adj + EE;

    static bool attr_set = false;
    if (!attr_set) {
        cudaFuncSetAttribute(k_gemm_mma,
                             cudaFuncAttributeMaxDynamicSharedMemorySize, GEMM_SMEM);
        attr_set = true;
    }

    // CSR build
    k_zero<<<(NN + 255) / 256, 256>>>();
    k_count<<<(EE / 4 + 255) / 256, 256>>>(dst);
    k_scan_a<<<NBLK, 1024>>>();
    k_scan_c<<<NBLK, 1024>>>();
    k_fill<<<(EE / 4 + 255) / 256, 256>>>(src, dst);

    // GEMM (mma.sync bf16 split)
    k_gemm_mma<<<(NN + 127) / 128, 256, GEMM_SMEM>>>(x, W);

    // fused gather + self loop + bias + relu
    k_gather<<<(NN / 2 + 7) / 8, 256>>>(b, out);
}

// round 7
// speedup vs baseline: 1.2601x; 1.2601x over previous
#include <cuda_runtime.h>
#include <cuda_bf16.h>
#include <cstdint>

// Problem constants (match reference_code)
#define NN 50000
#define EE 800000
#define FIN 256
#define FOUT 64

#define NBLK 49   // ceil(NN / 1024)

// Scratch (no cudaMalloc allowed) — static __device__ globals.
__device__ int   g_cnt[NN];          // in-degree (w/o self loop)
__device__ int   g_fill[NN];         // bucket fill cursor (pre-init to offsets)
__device__ int   g_off[NN + 1];      // CSR offsets
__device__ int   g_bsum[64];         // per-block sums for scan
__device__ int2  g_nbr2[EE];         // CSR: {src node, norm bits} per incoming edge
__device__ float g_deg[NN];          // dinv = rsqrt(deg)
__device__ float g_h[NN * FOUT];     // h = x @ W

// ---------------------------------------------------------------------------
__device__ __forceinline__ uint32_t pk2(float lo, float hi) {
    uint32_t d;
    asm("cvt.rn.bf16x2.f32 %0, %1, %2;" : "=r"(d) : "f"(hi), "f"(lo));
    return d;
}
__device__ __forceinline__ float f_lo16(uint32_t u) { return __uint_as_float(u << 16); }
__device__ __forceinline__ float f_hi16(uint32_t u) { return __uint_as_float(u & 0xffff0000u); }

// ---------------------------------------------------------------------------
// K1: zero counters
__global__ void k_zero() {
    int i = blockIdx.x * blockDim.x + threadIdx.x;
    if (i < NN) g_cnt[i] = 0;
}

// K2: in-degree count over edge dst (4 edges/thread, int4 loads)
__global__ void k_count(const int* __restrict__ dst) {
    int e0 = (blockIdx.x * blockDim.x + threadIdx.x) * 4;
    if (e0 >= EE) return;
    int4 d4 = *reinterpret_cast<const int4*>(dst + e0);
    atomicAdd(&g_cnt[d4.x], 1);
    atomicAdd(&g_cnt[d4.y], 1);
    atomicAdd(&g_cnt[d4.z], 1);
    atomicAdd(&g_cnt[d4.w], 1);
}

// K3a: per-block (1024 elems) sums, coalesced
__global__ __launch_bounds__(1024) void k_scan_a() {
    __shared__ int ws[32];
    const int t = threadIdx.x;
    int idx = blockIdx.x * 1024 + t;
    int v = (idx < NN) ? g_cnt[idx] : 0;
    for (int o = 16; o > 0; o >>= 1) v += __shfl_down_sync(0xffffffffu, v, o);
    if ((t & 31) == 0) ws[t >> 5] = v;
    __syncthreads();
    if (t < 32) {
        int s = ws[t];
        for (int o = 16; o > 0; o >>= 1) s += __shfl_down_sync(0xffffffffu, s, o);
        if (t == 0) g_bsum[blockIdx.x] = s;
    }
}

// K3b: per-block exclusive scan -> g_off, g_fill (cursor), g_deg.
// Each block computes its own global prefix from g_bsum (warp 1), no extra kernel.
__global__ __launch_bounds__(1024) void k_scan_c() {
    __shared__ int ws[32];
    __shared__ int bpre_s;
    const int t = threadIdx.x;
    const int lane = t & 31;
    const int wid = t >> 5;
    int idx = blockIdx.x * 1024 + t;
    int c = (idx < NN) ? g_cnt[idx] : 0;

    // per-warp inclusive scan
    int incl = c;
    for (int o = 1; o < 32; o <<= 1) {
        int u = __shfl_up_sync(0xffffffffu, incl, o);
        if (lane >= o) incl += u;
    }
    if (lane == 31) ws[wid] = incl;

    // warp 1: this block's global prefix (sum of earlier block sums)
    if (wid == 1) {
        int accp = 0;
        for (int j = lane; j < blockIdx.x; j += 32) accp += g_bsum[j];
        for (int o = 16; o > 0; o >>= 1) accp += __shfl_down_sync(0xffffffffu, accp, o);
        if (lane == 0) bpre_s = accp;
    }
    __syncthreads();
    if (wid == 0) {
        int wv = ws[lane];
        for (int o = 1; o < 32; o <<= 1) {
            int u = __shfl_up_sync(0xffffffffu, wv, o);
            if (lane >= o) wv += u;
        }
        ws[lane] = wv;
    }
    __syncthreads();
    int excl = incl - c + (wid ? ws[wid - 1] : 0);

    if (idx < NN) {
        int off = bpre_s + excl;
        g_off[idx]  = off;
        g_fill[idx] = off;
        g_deg[idx]  = rsqrtf((float)(c + 1));
    }
    if (blockIdx.x == 0 && t == 0) g_off[NN] = EE;
}

// K4: bucket fill — cursor holds offsets; 4 edges/thread; fuse norm compute.
__global__ void k_fill(const int* __restrict__ src, const int* __restrict__ dst) {
    int e0 = (blockIdx.x * blockDim.x + threadIdx.x) * 4;
    if (e0 >= EE) return;
    int4 s4 = *reinterpret_cast<const int4*>(src + e0);
    int4 d4 = *reinterpret_cast<const int4*>(dst + e0);
    float ds0 = g_deg[s4.x], ds1 = g_deg[s4.y], ds2 = g_deg[s4.z], ds3 = g_deg[s4.w];
    float dd0 = g_deg[d4.x], dd1 = g_deg[d4.y], dd2 = g_deg[d4.z], dd3 = g_deg[d4.w];
    int p0 = atomicAdd(&g_fill[d4.x], 1);
    int p1 = atomicAdd(&g_fill[d4.y], 1);
    int p2 = atomicAdd(&g_fill[d4.z], 1);
    int p3 = atomicAdd(&g_fill[d4.w], 1);
    g_nbr2[p0] = make_int2(s4.x, __float_as_int(ds0 * dd0));
    g_nbr2[p1] = make_int2(s4.y, __float_as_int(ds1 * dd1));
    g_nbr2[p2] = make_int2(s4.z, __float_as_int(ds2 * dd2));
    g_nbr2[p3] = make_int2(s4.w, __float_as_int(ds3 * dd3));
}

// ---------------------------------------------------------------------------
// K5: mma.sync bf16 GEMM  h = x @ W  with split-bf16 (proven R3 shape:
// 512 threads, 16 warps = 8 m-stripes x 2 n-halves, acc[4][4], ~62 regs).
// Only change vs R3: conversions use cvt.rn.bf16x2.f32 packing.

#define PAD_K 264   // 256 + 8 pad: conflict-free b-frag LDS
#define B_HI_OFF 0
#define B_LO_OFF (64 * PAD_K)               // in ushort units
#define GEMM_SMEM (2 * 64 * PAD_K * 2)      // bytes = 67584

__device__ __forceinline__ void mma_bf16(float* c, const uint32_t* a, uint32_t b0, uint32_t b1) {
    asm volatile(
        "mma.sync.aligned.m16n8k16.row.col.f32.bf16.bf16.f32 "
        "{%0,%1,%2,%3}, {%4,%5,%6,%7}, {%8,%9}, {%0,%1,%2,%3};"
        : "+f"(c[0]), "+f"(c[1]), "+f"(c[2]), "+f"(c[3])
        : "r"(a[0]), "r"(a[1]), "r"(a[2]), "r"(a[3]), "r"(b0), "r"(b1));
}

__global__ __launch_bounds__(512, 2) void k_gemm_mma(
    const float* __restrict__ x, const float* __restrict__ W)
{
    extern __shared__ __align__(16) ushort Bs[];   // [2][64][PAD_K] bf16 bits

    const int t    = threadIdx.x;
    const int wid  = t >> 5;
    const int lane = t & 31;
    const int g    = lane >> 2;
    const int tig  = lane & 3;

    // ---- stage W -> smem bf16 hi/lo, [n][k] layout ----
#pragma unroll 8
    for (int it = 0; it < 32; ++it) {
        int idx = t + it * 512;
        int k = idx >> 6;
        int n = idx & 63;
        float w = W[k * FOUT + n];
        uint32_t hp = pk2(w, 0.f);
        Bs[B_HI_OFF + n * PAD_K + k] = (ushort)(hp & 0xffffu);
        Bs[B_LO_OFF + n * PAD_K + k] =
            (ushort)(pk2(w - f_lo16(hp), 0.f) & 0xffffu);
    }
    __syncthreads();

    // ---- warp tiling ----
    const int stripe = wid & 7;
    const int nhalf  = wid >> 3;
    const int row0   = blockIdx.x * 128 + stripe * 16;

    const int row1 = row0 + g;
    const int row2 = row1 + 8;
    const bool v1 = (row1 < NN);
    const bool v2 = (row2 < NN);
    const float* xr1 = x + (size_t)row1 * FIN;
    const float* xr2 = x + (size_t)row2 * FIN;

    float acc[4][4];
#pragma unroll
    for (int i = 0; i < 4; ++i)
#pragma unroll
        for (int j = 0; j < 4; ++j) acc[i][j] = 0.0f;

#pragma unroll 4
    for (int s = 0; s < 16; ++s) {
        const int kb = s * 16 + tig * 2;

        float2 p0 = v1 ? *reinterpret_cast<const float2*>(xr1 + kb)     : make_float2(0.f, 0.f);
        float2 p1 = v2 ? *reinterpret_cast<const float2*>(xr2 + kb)     : make_float2(0.f, 0.f);
        float2 p2 = v1 ? *reinterpret_cast<const float2*>(xr1 + kb + 8) : make_float2(0.f, 0.f);
        float2 p3 = v2 ? *reinterpret_cast<const float2*>(xr2 + kb + 8) : make_float2(0.f, 0.f);

        uint32_t a_hi[4], a_lo[4];
        a_hi[0] = pk2(p0.x, p0.y); a_lo[0] = pk2(p0.x - f_lo16(a_hi[0]), p0.y - f_hi16(a_hi[0]));
        a_hi[1] = pk2(p1.x, p1.y); a_lo[1] = pk2(p1.x - f_lo16(a_hi[1]), p1.y - f_hi16(a_hi[1]));
        a_hi[2] = pk2(p2.x, p2.y); a_lo[2] = pk2(p2.x - f_lo16(a_hi[2]), p2.y - f_hi16(a_hi[2]));
        a_hi[3] = pk2(p3.x, p3.y); a_lo[3] = pk2(p3.x - f_lo16(a_hi[3]), p3.y - f_hi16(a_hi[3]));

#pragma unroll
        for (int nt = 0; nt < 4; ++nt) {
            int n = nhalf * 32 + nt * 8 + g;
            const ushort* bh = &Bs[B_HI_OFF + n * PAD_K + kb];
            const ushort* bl = &Bs[B_LO_OFF + n * PAD_K + kb];
            uint32_t bh0 = *reinterpret_cast<const uint32_t*>(bh);
            uint32_t bh1 = *reinterpret_cast<const uint32_t*>(bh + 8);
            uint32_t bl0 = *reinterpret_cast<const uint32_t*>(bl);
            uint32_t bl1 = *reinterpret_cast<const uint32_t*>(bl + 8);
            mma_bf16(acc[nt], a_hi, bh0, bh1);
            mma_bf16(acc[nt], a_hi, bl0, bl1);
            mma_bf16(acc[nt], a_lo, bh0, bh1);
        }
    }

    // ---- epilogue: write h ----
#pragma unroll
    for (int nt = 0; nt < 4; ++nt) {
        int c0 = nhalf * 32 + nt * 8 + tig * 2;
        if (v1)
            *reinterpret_cast<float2*>(&g_h[(size_t)row1 * FOUT + c0]) =
                make_float2(acc[nt][0], acc[nt][1]);
        if (v2)
            *reinterpret_cast<float2*>(&g_h[(size_t)row2 * FOUT + c0]) =
                make_float2(acc[nt][2], acc[nt][3]);
    }
}

// ---------------------------------------------------------------------------
// K6: CSR gather. 2 nodes/warp (16 lanes x float4), norm pre-fused in g_nbr2,
// neighbor loop unrolled x4.
__global__ __launch_bounds__(256) void k_gather(
    const float* __restrict__ bias, float* __restrict__ out)
{
    const int warp = blockIdx.x * 8 + (threadIdx.x >> 5);
    const int lane = threadIdx.x & 31;
    const int half = lane >> 4;
    const int hl   = lane & 15;
    const int node = warp * 2 + half;
    if (node >= NN) return;

    const float dinv = g_deg[node];
    const int beg = g_off[node];
    const int end = g_off[node + 1];

    // self-loop term: h[node] * dinv^2
    float4 a = *reinterpret_cast<const float4*>(&g_h[(size_t)node * FOUT + hl * 4]);
    const float sl = dinv * dinv;
    a.x *= sl; a.y *= sl; a.z *= sl; a.w *= sl;

    int j = beg;
    for (; j + 4 <= end; j += 4) {
        int2 e0 = g_nbr2[j];
        int2 e1 = g_nbr2[j + 1];
        int2 e2 = g_nbr2[j + 2];
        int2 e3 = g_nbr2[j + 3];
        float4 v0 = *reinterpret_cast<const float4*>(&g_h[(size_t)e0.x * FOUT + hl * 4]);
        float4 v1 = *reinterpret_cast<const float4*>(&g_h[(size_t)e1.x * FOUT + hl * 4]);
        float4 v2 = *reinterpret_cast<const float4*>(&g_h[(size_t)e2.x * FOUT + hl * 4]);
        float4 v3 = *reinterpret_cast<const float4*>(&g_h[(size_t)e3.x * FOUT + hl * 4]);
        float n0 = __int_as_float(e0.y), n1 = __int_as_float(e1.y);
        float n2 = __int_as_float(e2.y), n3 = __int_as_float(e3.y);
        a.x = fmaf(v0.x, n0, a.x); a.y = fmaf(v0.y, n0, a.y);
        a.z = fmaf(v0.z, n0, a.z); a.w = fmaf(v0.w, n0, a.w);
        a.x = fmaf(v1.x, n1, a.x); a.y = fmaf(v1.y, n1, a.y);
        a.z = fmaf(v1.z, n1, a.z); a.w = fmaf(v1.w, n1, a.w);
        a.x = fmaf(v2.x, n2, a.x); a.y = fmaf(v2.y, n2, a.y);
        a.z = fmaf(v2.z, n2, a.z); a.w = fmaf(v2.w, n2, a.w);
        a.x = fmaf(v3.x, n3, a.x); a.y = fmaf(v3.y, n3, a.y);
        a.z = fmaf(v3.z, n3, a.z); a.w = fmaf(v3.w, n3, a.w);
    }
    for (; j < end; ++j) {
        int2 e0 = g_nbr2[j];
        float n0 = __int_as_float(e0.y);
        float4 v0 = *reinterpret_cast<const float4*>(&g_h[(size_t)e0.x * FOUT + hl * 4]);
        a.x = fmaf(v0.x, n0, a.x); a.y = fmaf(v0.y, n0, a.y);
        a.z = fmaf(v0.z, n0, a.z); a.w = fmaf(v0.w, n0, a.w);
    }

    float4 bb = *reinterpret_cast<const float4*>(bias + hl * 4);
    a.x = fmaxf(a.x + bb.x, 0.f);
    a.y = fmaxf(a.y + bb.y, 0.f);
    a.z = fmaxf(a.z + bb.z, 0.f);
    a.w = fmaxf(a.w + bb.w, 0.f);
    *reinterpret_cast<float4*>(&out[(size_t)node * FOUT + hl * 4]) = a;
}

// ---------------------------------------------------------------------------
extern "C" void kernel_launch(void* const* d_in, const int* in_sizes, int n_in,
                              void* d_out, int out_size)
{
    const float* x   = (const float*)d_in[0];   // [N, 256]
    const int*   adj = (const int*)d_in[1];     // [2, E]
    const float* W   = (const float*)d_in[2];   // [256, 64]
    const float* b   = (const float*)d_in[3];   // [64]
    float*       out = (float*)d_out;           // [N, 64]

    const int* src = adj;
    const int* dst = adj + EE;

    static bool attr_set = false;
    if (!attr_set) {
        cudaFuncSetAttribute(k_gemm_mma,
                             cudaFuncAttributeMaxDynamicSharedMemorySize, GEMM_SMEM);
        attr_set = true;
    }

    // CSR build; GEMM is independent and placed 4th so ncu profiles it.
    k_zero<<<(NN + 255) / 256, 256>>>();
    k_count<<<(EE / 4 + 255) / 256, 256>>>(dst);
    k_scan_a<<<NBLK, 1024>>>();
    k_gemm_mma<<<(NN + 127) / 128, 512, GEMM_SMEM>>>(x, W);   // 4th launch
    k_scan_c<<<NBLK, 1024>>>();
    k_fill<<<(EE / 4 + 255) / 256, 256>>>(src, dst);

    // fused gather + self loop + bias + relu
    k_gather<<<(NN / 2 + 7) / 8, 256>>>(b, out);
}